// round 5
// baseline (speedup 1.0000x reference)
#include <cuda_runtime.h>
#include <cuda_fp16.h>
#include <cstdint>

#define B_  2
#define C_  256
#define H8  56
#define W8  96
#define HW  5376            // H8*W8
#define NQ  (B_*HW)         // 10752 query rows (batch-major)

// ---------------- scratch (static __device__, no allocations) ----------------
__device__ __align__(128) __half g_f1[B_*HW*C_];   // fmap1 [b][n][c] fp16
__device__ __align__(128) __half g_f2[B_*HW*C_];   // fmap2 [b][m][c] fp16
__device__ __align__(128) __half g_c0[57802752];   // 2*5376*5376 level-0 corr
__device__ __align__(128) __half g_c1[NQ*28*48];
__device__ __align__(128) __half g_c2[NQ*14*24];
__device__ __align__(128) __half g_c3[NQ*7*12];

// ---------------- helpers ----------------
__device__ __forceinline__ uint32_t smem_u32(const void* p) {
    return (uint32_t)__cvta_generic_to_shared(p);
}
__device__ __forceinline__ void ldm4(uint32_t& r0, uint32_t& r1, uint32_t& r2, uint32_t& r3,
                                     uint32_t addr) {
    asm volatile("ldmatrix.sync.aligned.m8n8.x4.shared.b16 {%0,%1,%2,%3}, [%4];"
                 : "=r"(r0), "=r"(r1), "=r"(r2), "=r"(r3) : "r"(addr));
}
__device__ __forceinline__ void mma16816(float* c, const uint32_t* a, const uint32_t* b) {
    asm volatile(
        "mma.sync.aligned.m16n8k16.row.col.f32.f16.f16.f32 "
        "{%0,%1,%2,%3},{%4,%5,%6,%7},{%8,%9},{%0,%1,%2,%3};"
        : "+f"(c[0]), "+f"(c[1]), "+f"(c[2]), "+f"(c[3])
        : "r"(a[0]), "r"(a[1]), "r"(a[2]), "r"(a[3]), "r"(b[0]), "r"(b[1]));
}
__device__ __forceinline__ void cpasync16(uint32_t dst, const void* src) {
    asm volatile("cp.async.cg.shared.global [%0], [%1], 16;" :: "r"(dst), "l"(src));
}
__device__ __forceinline__ void cp_commit() {
    asm volatile("cp.async.commit_group;" ::: "memory");
}
template<int N> __device__ __forceinline__ void cp_wait() {
    asm volatile("cp.async.wait_group %0;" :: "n"(N) : "memory");
}

// empty kernel: shifts the profiled launch index onto k_gemm (diagnostics)
__global__ void k_nop() {}

// ---------------- 1) transpose + fp16 convert: [B,C,H,W] -> [B,HW,C] ----------------
__global__ void k_convert(const float* __restrict__ f1, const float* __restrict__ f2) {
    __shared__ float tile[32][33];
    int t = blockIdx.z >> 1;
    int b = blockIdx.z & 1;
    const float* src = t ? f2 : f1;
    __half* dst = t ? g_f2 : g_f1;
    int n0 = blockIdx.x * 32, c0 = blockIdx.y * 32;
    int tx = threadIdx.x, ty = threadIdx.y;
    tile[ty][tx] = src[(size_t)(b * C_ + c0 + ty) * HW + n0 + tx];
    __syncthreads();
    dst[(size_t)(b * HW + n0 + ty) * C_ + c0 + tx] = __float2half_rn(tile[tx][ty]);
}

// ---------------- 2) corr GEMM (HMMA, cp.async 3-stage pipeline) ----------------
#define SSTRIDE 40

__global__ __launch_bounds__(256) void k_gemm() {
    __shared__ __align__(16) __half As[3][128 * SSTRIDE];
    __shared__ __align__(16) __half Bs[3][128 * SSTRIDE];
    const int b  = blockIdx.z;
    const int bi = blockIdx.y;
    const int bj = blockIdx.x;
    const int tid  = threadIdx.x;
    const int lane = tid & 31;
    const int wid  = tid >> 5;
    const int wm = (wid & 1) * 64;
    const int wn = (wid >> 1) * 32;

    const __half* Ag = g_f1 + ((size_t)b * HW + (size_t)bi * 128) * C_;
    const __half* Bg = g_f2 + ((size_t)b * HW + (size_t)bj * 128) * C_;

    const int ldrow0 = tid >> 2;
    const int ldrow1 = (tid + 256) >> 2;
    const int ldc16  = (tid & 3) << 3;

    float acc[4][4][4];
#pragma unroll
    for (int i = 0; i < 4; i++)
#pragma unroll
        for (int j = 0; j < 4; j++)
#pragma unroll
            for (int k = 0; k < 4; k++) acc[i][j][k] = 0.f;

#define LOAD_STAGE(kt, s)                                                          \
    {                                                                              \
        const int k0 = (kt) * 32;                                                  \
        cpasync16(smem_u32(&As[s][ldrow0 * SSTRIDE + ldc16]),                      \
                  Ag + ldrow0 * C_ + k0 + ldc16);                                  \
        cpasync16(smem_u32(&As[s][ldrow1 * SSTRIDE + ldc16]),                      \
                  Ag + ldrow1 * C_ + k0 + ldc16);                                  \
        cpasync16(smem_u32(&Bs[s][ldrow0 * SSTRIDE + ldc16]),                      \
                  Bg + ldrow0 * C_ + k0 + ldc16);                                  \
        cpasync16(smem_u32(&Bs[s][ldrow1 * SSTRIDE + ldc16]),                      \
                  Bg + ldrow1 * C_ + k0 + ldc16);                                  \
        cp_commit();                                                               \
    }

    LOAD_STAGE(0, 0);
    LOAD_STAGE(1, 1);

#pragma unroll
    for (int kt = 0; kt < 8; kt++) {
        cp_wait<1>();
        __syncthreads();
        if (kt + 2 < 8) { LOAD_STAGE(kt + 2, (kt + 2) % 3); }
        else            { cp_commit(); }
        const __half* as = As[kt % 3];
        const __half* bs = Bs[kt % 3];
#pragma unroll
        for (int kk = 0; kk < 32; kk += 16) {
            uint32_t a[4][4], bf[4][2];
#pragma unroll
            for (int mi = 0; mi < 4; mi++) {
                int row = wm + mi * 16 + (lane & 15);
                int col = kk + ((lane >> 4) << 3);
                ldm4(a[mi][0], a[mi][1], a[mi][2], a[mi][3],
                     smem_u32(as + row * SSTRIDE + col));
            }
#pragma unroll
            for (int nb = 0; nb < 2; nb++) {
                int row = wn + nb * 16 + (lane & 7) + ((lane >> 4) << 3);
                int col = kk + (((lane >> 3) & 1) << 3);
                uint32_t r0, r1, r2, r3;
                ldm4(r0, r1, r2, r3, smem_u32(bs + row * SSTRIDE + col));
                bf[nb * 2][0] = r0; bf[nb * 2][1] = r1;
                bf[nb * 2 + 1][0] = r2; bf[nb * 2 + 1][1] = r3;
            }
#pragma unroll
            for (int mi = 0; mi < 4; mi++)
#pragma unroll
                for (int ni = 0; ni < 4; ni++)
                    mma16816(acc[mi][ni], a[mi], bf[ni]);
        }
        __syncthreads();
    }

    const float s = 0.0625f;   // 1/sqrt(256)
    const size_t rowbase = (size_t)b * HW;
#pragma unroll
    for (int mi = 0; mi < 4; mi++) {
#pragma unroll
        for (int ni = 0; ni < 4; ni++) {
            int r0 = bi * 128 + wm + mi * 16 + (lane >> 2);
            int c0 = bj * 128 + wn + ni * 8 + (lane & 3) * 2;
            __half2* p0 = (__half2*)(g_c0 + (rowbase + r0) * HW + c0);
            *p0 = __floats2half2_rn(acc[mi][ni][0] * s, acc[mi][ni][1] * s);
            __half2* p1 = (__half2*)(g_c0 + (rowbase + r0 + 8) * HW + c0);
            *p1 = __floats2half2_rn(acc[mi][ni][2] * s, acc[mi][ni][3] * s);
        }
    }
}

// ---------------- 3) fused pyramid pool: c0 row -> l1,l2,l3 ----------------
__global__ void k_pool_fused() {
    __shared__ __align__(16) __half s0[56 * 96];
    __shared__ __half s1[28 * 48];
    __shared__ __half s2[14 * 24];
    int n = blockIdx.x;
    int tid = threadIdx.x;
    const int4* src = (const int4*)(g_c0 + (size_t)n * 5376);
    int4* s0v = (int4*)s0;
#pragma unroll
    for (int i = tid; i < 672; i += 256) s0v[i] = src[i];
    __syncthreads();
    for (int i = tid; i < 1344; i += 256) {
        int x = i % 48, y = i / 48;
        float v = 0.25f * (__half2float(s0[(2 * y) * 96 + 2 * x]) +
                           __half2float(s0[(2 * y) * 96 + 2 * x + 1]) +
                           __half2float(s0[(2 * y + 1) * 96 + 2 * x]) +
                           __half2float(s0[(2 * y + 1) * 96 + 2 * x + 1]));
        __half h = __float2half_rn(v);
        s1[i] = h;
        g_c1[(size_t)n * 1344 + i] = h;
    }
    __syncthreads();
    for (int i = tid; i < 336; i += 256) {
        int x = i % 24, y = i / 24;
        float v = 0.25f * (__half2float(s1[(2 * y) * 48 + 2 * x]) +
                           __half2float(s1[(2 * y) * 48 + 2 * x + 1]) +
                           __half2float(s1[(2 * y + 1) * 48 + 2 * x]) +
                           __half2float(s1[(2 * y + 1) * 48 + 2 * x + 1]));
        __half h = __float2half_rn(v);
        s2[i] = h;
        g_c2[(size_t)n * 336 + i] = h;
    }
    __syncthreads();
    if (tid < 84) {
        int x = tid % 12, y = tid / 12;
        float v = 0.25f * (__half2float(s2[(2 * y) * 24 + 2 * x]) +
                           __half2float(s2[(2 * y) * 24 + 2 * x + 1]) +
                           __half2float(s2[(2 * y + 1) * 24 + 2 * x]) +
                           __half2float(s2[(2 * y + 1) * 24 + 2 * x + 1]));
        g_c3[(size_t)n * 84 + tid] = __float2half_rn(v);
    }
}

// ---------------- 4) pyramid sampling -> [B,324,H8,W8] ----------------
// Block = 32 consecutive pixels of one row, 256 threads.
// Phase 0: precompute per-(pixel,level) window metadata.
// Phase 1: cooperative cell-coalesced window gather (lanes = consecutive cells).
// Phase 2: 8 warps (2 per level), coalesced 128B stores across pixels.
__global__ __launch_bounds__(256) void k_sample(const float* __restrict__ coords,
                                                float* __restrict__ out) {
    __shared__ __half swin[4][100][32];
    __shared__ float swx[4][32], swy[4][32];
    __shared__ int sbx[4][32], sby[4][32];
    __shared__ uint32_t soff[4][32];

    int blk = blockIdx.x;            // 2*56*3 = 336
    int wseg = blk % 3;
    int h = (blk / 3) % H8;
    int b = blk / (3 * H8);
    int tid = threadIdx.x;

    if (tid < 128) {
        int p = tid & 31, L = tid >> 5;
        int w = wseg * 32 + p;
        int nq = h * W8 + w;
        float cx = coords[(size_t)(b * 2 + 0) * HW + nq];
        float cy = coords[(size_t)(b * 2 + 1) * HW + nq];
        float inv = 1.0f / (float)(1 << L);
        float fx = cx * inv, fy = cy * inv;
        float fxf = floorf(fx), fyf = floorf(fy);
        swx[L][p] = fx - fxf;
        swy[L][p] = fy - fyf;
        sbx[L][p] = (int)fxf - 4;
        sby[L][p] = (int)fyf - 4;
        int HlWl = (L == 0) ? 5376 : (L == 1) ? 1344 : (L == 2) ? 336 : 84;
        soff[L][p] = (uint32_t)(b * HW + nq) * (uint32_t)HlWl;
    }
    __syncthreads();

    // phase 1: 32p x 4L x 128 slots (cells 0..99 valid), lanes -> consecutive cells
    for (int i = tid; i < 16384; i += 256) {
        int cell = i & 127;
        if (cell < 100) {
            int L = (i >> 7) & 3;
            int p = i >> 9;
            int ly = cell / 10, lx = cell - ly * 10;
            const __half* cl; int Hl, Wl;
            if (L == 0)      { cl = g_c0; Hl = 56; Wl = 96; }
            else if (L == 1) { cl = g_c1; Hl = 28; Wl = 48; }
            else if (L == 2) { cl = g_c2; Hl = 14; Wl = 24; }
            else             { cl = g_c3; Hl = 7;  Wl = 12; }
            int gx = sbx[L][p] + lx;
            int gy = sby[L][p] + ly;
            __half v = __ushort_as_half((unsigned short)0);
            if (gx >= 0 && gx < Wl && gy >= 0 && gy < Hl)
                v = cl[soff[L][p] + gy * Wl + gx];
            swin[L][cell][p] = v;
        }
    }
    __syncthreads();

    // phase 2: 8 warps; warp -> (level, channel half); lanes -> pixels
    int lane = tid & 31, wid = tid >> 5;
    int L = wid >> 1;
    float wx = swx[L][lane], wy = swy[L][lane];
    int w = wseg * 32 + lane;
    float* outbase = out + ((size_t)(b * 324 + L * 81) * H8 + h) * W8 + w;
    int o0 = (wid & 1) ? 41 : 0;
    int oend = (wid & 1) ? 81 : 41;
    float omwx = 1.f - wx, omwy = 1.f - wy;
    for (int o = o0; o < oend; o++) {
        int xo = o / 9;              // x varies along axis 0 (torch meshgrid quirk)
        int yo = o - xo * 9;
        float v00 = __half2float(swin[L][yo * 10 + xo][lane]);
        float v10 = __half2float(swin[L][yo * 10 + xo + 1][lane]);
        float v01 = __half2float(swin[L][(yo + 1) * 10 + xo][lane]);
        float v11 = __half2float(swin[L][(yo + 1) * 10 + xo + 1][lane]);
        float v = omwy * (omwx * v00 + wx * v10) + wy * (omwx * v01 + wx * v11);
        outbase[(size_t)o * HW] = v;
    }
}

// ---------------- 5) convex upsample -> [B,2,448,768] ----------------
__global__ void k_up(const float* __restrict__ flow, const float* __restrict__ mask,
                     float* __restrict__ out) {
    int id = blockIdx.x;
    int rs = id & 63;
    int bh = id >> 6;
    int h = bh % H8;
    int b = bh / H8;
    int w = threadIdx.x;
    int r = rs >> 3, s = rs & 7;

    float f0[9], f1v[9];
#pragma unroll
    for (int k = 0; k < 9; k++) {
        int i = k / 3 - 1, j = k % 3 - 1;
        int hh = h + i, ww = w + j;
        bool ok = (hh >= 0 && hh < H8 && ww >= 0 && ww < W8);
        f0[k]  = ok ? flow[((size_t)(b * 2 + 0) * H8 + hh) * W8 + ww] : 0.f;
        f1v[k] = ok ? flow[((size_t)(b * 2 + 1) * H8 + hh) * W8 + ww] : 0.f;
    }
    float e[9], sum = 0.f;
#pragma unroll
    for (int k = 0; k < 9; k++) {
        e[k] = __expf(mask[((size_t)(b * 576 + k * 64 + rs) * H8 + h) * W8 + w]);
        sum += e[k];
    }
    float a0 = 0.f, a1 = 0.f;
#pragma unroll
    for (int k = 0; k < 9; k++) { a0 += e[k] * f0[k]; a1 += e[k] * f1v[k]; }
    float inv = 8.0f / sum;
    int y = h * 8 + r, x = w * 8 + s;
    out[((size_t)(b * 2 + 0) * 448 + y) * 768 + x] = a0 * inv;
    out[((size_t)(b * 2 + 1) * 448 + y) * 768 + x] = a1 * inv;
}

// ---------------- launcher ----------------
extern "C" void kernel_launch(void* const* d_in, const int* in_sizes, int n_in,
                              void* d_out, int out_size) {
    const float* fmap1  = (const float*)d_in[0];
    const float* fmap2  = (const float*)d_in[1];
    const float* coords = (const float*)d_in[2];
    const float* flow   = (const float*)d_in[3];
    const float* mask   = (const float*)d_in[4];
    float* out = (float*)d_out;
    float* out_up = out + (size_t)B_ * 324 * HW;

    dim3 cb(32, 32);
    k_convert<<<dim3(HW / 32, C_ / 32, 4), cb>>>(fmap1, fmap2);     // idx 0
    k_nop<<<1, 32>>>();                                             // idx 1
    k_nop<<<1, 32>>>();                                             // idx 2
    k_gemm<<<dim3(42, 42, 2), 256>>>();                             // idx 3 (profiled)
    k_pool_fused<<<NQ, 256>>>();                                    // idx 4
    k_sample<<<336, 256>>>(coords, out);                            // idx 5
    k_up<<<NQ * 64 / W8, W8>>>(flow, mask, out_up);                 // idx 6
}

// round 6
// speedup vs baseline: 1.1471x; 1.1471x over previous
#include <cuda_runtime.h>
#include <cuda_fp16.h>
#include <cstdint>

#define B_  2
#define C_  256
#define H8  56
#define W8  96
#define HW  5376            // H8*W8
#define NQ  (B_*HW)         // 10752 query rows (batch-major)

// ---------------- scratch (static __device__, no allocations) ----------------
__device__ __align__(128) __half g_f1[B_*HW*C_];   // fmap1 [b][n][c] fp16
__device__ __align__(128) __half g_f2[B_*HW*C_];   // fmap2 [b][m][c] fp16
__device__ __align__(128) __half g_c0[57802752];   // 2*5376*5376 level-0 corr
__device__ __align__(128) __half g_c1[NQ*28*48];
__device__ __align__(128) __half g_c2[NQ*14*24];
__device__ __align__(128) __half g_c3[NQ*7*12];

// ---------------- helpers ----------------
__device__ __forceinline__ uint32_t smem_u32(const void* p) {
    return (uint32_t)__cvta_generic_to_shared(p);
}
__device__ __forceinline__ void ldm4(uint32_t& r0, uint32_t& r1, uint32_t& r2, uint32_t& r3,
                                     uint32_t addr) {
    asm volatile("ldmatrix.sync.aligned.m8n8.x4.shared.b16 {%0,%1,%2,%3}, [%4];"
                 : "=r"(r0), "=r"(r1), "=r"(r2), "=r"(r3) : "r"(addr));
}
__device__ __forceinline__ void mma16816(float* c, const uint32_t* a, const uint32_t* b) {
    asm volatile(
        "mma.sync.aligned.m16n8k16.row.col.f32.f16.f16.f32 "
        "{%0,%1,%2,%3},{%4,%5,%6,%7},{%8,%9},{%0,%1,%2,%3};"
        : "+f"(c[0]), "+f"(c[1]), "+f"(c[2]), "+f"(c[3])
        : "r"(a[0]), "r"(a[1]), "r"(a[2]), "r"(a[3]), "r"(b[0]), "r"(b[1]));
}
__device__ __forceinline__ void cpasync16(uint32_t dst, const void* src) {
    asm volatile("cp.async.cg.shared.global [%0], [%1], 16;" :: "r"(dst), "l"(src));
}
__device__ __forceinline__ void cp_commit() {
    asm volatile("cp.async.commit_group;" ::: "memory");
}
template<int N> __device__ __forceinline__ void cp_wait() {
    asm volatile("cp.async.wait_group %0;" :: "n"(N) : "memory");
}

// ---------------- 1) transpose + fp16 convert: [B,C,H,W] -> [B,HW,C] ----------------
__global__ void k_convert(const float* __restrict__ f1, const float* __restrict__ f2) {
    __shared__ float tile[32][33];
    int t = blockIdx.z >> 1;
    int b = blockIdx.z & 1;
    const float* src = t ? f2 : f1;
    __half* dst = t ? g_f2 : g_f1;
    int n0 = blockIdx.x * 32, c0 = blockIdx.y * 32;
    int tx = threadIdx.x, ty = threadIdx.y;
    tile[ty][tx] = src[(size_t)(b * C_ + c0 + ty) * HW + n0 + tx];
    __syncthreads();
    dst[(size_t)(b * HW + n0 + ty) * C_ + c0 + tx] = __float2half_rn(tile[tx][ty]);
}

// ---------------- 2) corr GEMM (HMMA, cp.async 4-stage pipeline, 1 sync/chunk) ----------
#define SSTRIDE 40

__global__ __launch_bounds__(256, 2) void k_gemm() {
    __shared__ __align__(16) __half As[4][128 * SSTRIDE];
    __shared__ __align__(16) __half Bs[4][128 * SSTRIDE];
    const int b  = blockIdx.z;
    const int bi = blockIdx.y;
    const int bj = blockIdx.x;
    const int tid  = threadIdx.x;
    const int lane = tid & 31;
    const int wid  = tid >> 5;
    const int wm = (wid & 1) * 64;
    const int wn = (wid >> 1) * 32;

    const __half* Ag = g_f1 + ((size_t)b * HW + (size_t)bi * 128) * C_;
    const __half* Bg = g_f2 + ((size_t)b * HW + (size_t)bj * 128) * C_;

    const int ldrow0 = tid >> 2;
    const int ldrow1 = (tid + 256) >> 2;
    const int ldc16  = (tid & 3) << 3;

    float acc[4][4][4];
#pragma unroll
    for (int i = 0; i < 4; i++)
#pragma unroll
        for (int j = 0; j < 4; j++)
#pragma unroll
            for (int k = 0; k < 4; k++) acc[i][j][k] = 0.f;

#define LOAD_STAGE(kt, s)                                                          \
    {                                                                              \
        const int k0 = (kt) * 32;                                                  \
        cpasync16(smem_u32(&As[s][ldrow0 * SSTRIDE + ldc16]),                      \
                  Ag + ldrow0 * C_ + k0 + ldc16);                                  \
        cpasync16(smem_u32(&As[s][ldrow1 * SSTRIDE + ldc16]),                      \
                  Ag + ldrow1 * C_ + k0 + ldc16);                                  \
        cpasync16(smem_u32(&Bs[s][ldrow0 * SSTRIDE + ldc16]),                      \
                  Bg + ldrow0 * C_ + k0 + ldc16);                                  \
        cpasync16(smem_u32(&Bs[s][ldrow1 * SSTRIDE + ldc16]),                      \
                  Bg + ldrow1 * C_ + k0 + ldc16);                                  \
        cp_commit();                                                               \
    }

    LOAD_STAGE(0, 0);
    LOAD_STAGE(1, 1);
    LOAD_STAGE(2, 2);

#pragma unroll
    for (int kt = 0; kt < 8; kt++) {
        cp_wait<2>();
        __syncthreads();     // all warps done with chunk kt-1 -> buffer (kt+3)&3 reusable
        if (kt + 3 < 8) { LOAD_STAGE(kt + 3, (kt + 3) & 3); }
        else            { cp_commit(); }
        const __half* as = As[kt & 3];
        const __half* bs = Bs[kt & 3];
#pragma unroll
        for (int kk = 0; kk < 32; kk += 16) {
            uint32_t a[4][4], bf[4][2];
#pragma unroll
            for (int mi = 0; mi < 4; mi++) {
                int row = wm + mi * 16 + (lane & 15);
                int col = kk + ((lane >> 4) << 3);
                ldm4(a[mi][0], a[mi][1], a[mi][2], a[mi][3],
                     smem_u32(as + row * SSTRIDE + col));
            }
#pragma unroll
            for (int nb = 0; nb < 2; nb++) {
                int row = wn + nb * 16 + (lane & 7) + ((lane >> 4) << 3);
                int col = kk + (((lane >> 3) & 1) << 3);
                uint32_t r0, r1, r2, r3;
                ldm4(r0, r1, r2, r3, smem_u32(bs + row * SSTRIDE + col));
                bf[nb * 2][0] = r0; bf[nb * 2][1] = r1;
                bf[nb * 2 + 1][0] = r2; bf[nb * 2 + 1][1] = r3;
            }
#pragma unroll
            for (int mi = 0; mi < 4; mi++)
#pragma unroll
                for (int ni = 0; ni < 4; ni++)
                    mma16816(acc[mi][ni], a[mi], bf[ni]);
        }
    }

    const float s = 0.0625f;   // 1/sqrt(256)
    const size_t rowbase = (size_t)b * HW;
#pragma unroll
    for (int mi = 0; mi < 4; mi++) {
#pragma unroll
        for (int ni = 0; ni < 4; ni++) {
            int r0 = bi * 128 + wm + mi * 16 + (lane >> 2);
            int c0 = bj * 128 + wn + ni * 8 + (lane & 3) * 2;
            __half2* p0 = (__half2*)(g_c0 + (rowbase + r0) * HW + c0);
            *p0 = __floats2half2_rn(acc[mi][ni][0] * s, acc[mi][ni][1] * s);
            __half2* p1 = (__half2*)(g_c0 + (rowbase + r0 + 8) * HW + c0);
            *p1 = __floats2half2_rn(acc[mi][ni][2] * s, acc[mi][ni][3] * s);
        }
    }
}

// ---------------- 3) fused pyramid pool: c0 row -> l1,l2,l3 ----------------
__global__ void k_pool_fused() {
    __shared__ __align__(16) __half s0[56 * 96];
    __shared__ __half s1[28 * 48];
    __shared__ __half s2[14 * 24];
    int n = blockIdx.x;
    int tid = threadIdx.x;
    const int4* src = (const int4*)(g_c0 + (size_t)n * 5376);
    int4* s0v = (int4*)s0;
#pragma unroll
    for (int i = tid; i < 672; i += 256) s0v[i] = src[i];
    __syncthreads();
    for (int i = tid; i < 1344; i += 256) {
        int x = i % 48, y = i / 48;
        float v = 0.25f * (__half2float(s0[(2 * y) * 96 + 2 * x]) +
                           __half2float(s0[(2 * y) * 96 + 2 * x + 1]) +
                           __half2float(s0[(2 * y + 1) * 96 + 2 * x]) +
                           __half2float(s0[(2 * y + 1) * 96 + 2 * x + 1]));
        __half h = __float2half_rn(v);
        s1[i] = h;
        g_c1[(size_t)n * 1344 + i] = h;
    }
    __syncthreads();
    for (int i = tid; i < 336; i += 256) {
        int x = i % 24, y = i / 24;
        float v = 0.25f * (__half2float(s1[(2 * y) * 48 + 2 * x]) +
                           __half2float(s1[(2 * y) * 48 + 2 * x + 1]) +
                           __half2float(s1[(2 * y + 1) * 48 + 2 * x]) +
                           __half2float(s1[(2 * y + 1) * 48 + 2 * x + 1]));
        __half h = __float2half_rn(v);
        s2[i] = h;
        g_c2[(size_t)n * 336 + i] = h;
    }
    __syncthreads();
    if (tid < 84) {
        int x = tid % 12, y = tid / 12;
        float v = 0.25f * (__half2float(s2[(2 * y) * 24 + 2 * x]) +
                           __half2float(s2[(2 * y) * 24 + 2 * x + 1]) +
                           __half2float(s2[(2 * y + 1) * 24 + 2 * x]) +
                           __half2float(s2[(2 * y + 1) * 24 + 2 * x + 1]));
        g_c3[(size_t)n * 84 + tid] = __float2half_rn(v);
    }
}

// ---------------- 4) pyramid sampling, coalesced stores -> [B,324,H8,W8] ----------------
// Block = 32 consecutive pixels of one row x 4 level-warps (R4 version).
__global__ __launch_bounds__(128) void k_sample(const float* __restrict__ coords,
                                                float* __restrict__ out) {
    __shared__ __half swin[4][100][32];
    int blk = blockIdx.x;            // 2*56*3 = 336
    int wseg = blk % 3;
    int h = (blk / 3) % H8;
    int b = blk / (3 * H8);
    int tx = threadIdx.x;            // pixel within 32-segment
    int L  = threadIdx.y;            // level
    int w = wseg * 32 + tx;
    int nq = h * W8 + w;

    float cx = coords[(size_t)(b * 2 + 0) * HW + nq];
    float cy = coords[(size_t)(b * 2 + 1) * HW + nq];

    const __half* cl; int Hl, Wl;
    if (L == 0)      { cl = g_c0; Hl = 56; Wl = 96; }
    else if (L == 1) { cl = g_c1; Hl = 28; Wl = 48; }
    else if (L == 2) { cl = g_c2; Hl = 14; Wl = 24; }
    else             { cl = g_c3; Hl = 7;  Wl = 12; }

    float inv = 1.0f / (float)(1 << L);
    float fx = cx * inv, fy = cy * inv;
    float fxf = floorf(fx), fyf = floorf(fy);
    float wx = fx - fxf, wy = fy - fyf;
    int bx = (int)fxf - 4, by = (int)fyf - 4;

    const __half* base = cl + (size_t)(b * HW + nq) * (Hl * Wl);
#pragma unroll
    for (int ly = 0; ly < 10; ly++) {
        int gy = by + ly;
        bool yok = (gy >= 0) & (gy < Hl);
        const __half* rowp = base + gy * Wl;
#pragma unroll
        for (int lx = 0; lx < 10; lx++) {
            int gx = bx + lx;
            __half v = __float2half_rn(0.f);
            if (yok && gx >= 0 && gx < Wl) v = rowp[gx];
            swin[L][ly * 10 + lx][tx] = v;
        }
    }
    __syncthreads();

    float* outbase = out + ((size_t)(b * 324 + L * 81) * H8 + h) * W8 + w;
#pragma unroll 3
    for (int o = 0; o < 81; o++) {
        int xo = o / 9;              // x varies along axis 0 (torch meshgrid quirk)
        int yo = o % 9;
        float v00 = __half2float(swin[L][yo * 10 + xo][tx]);
        float v10 = __half2float(swin[L][yo * 10 + xo + 1][tx]);
        float v01 = __half2float(swin[L][(yo + 1) * 10 + xo][tx]);
        float v11 = __half2float(swin[L][(yo + 1) * 10 + xo + 1][tx]);
        float v = (1.f - wy) * ((1.f - wx) * v00 + wx * v10)
                +        wy  * ((1.f - wx) * v01 + wx * v11);
        outbase[(size_t)o * HW] = v;
    }
}

// ---------------- 5) convex upsample -> [B,2,448,768] ----------------
__global__ void k_up(const float* __restrict__ flow, const float* __restrict__ mask,
                     float* __restrict__ out) {
    int id = blockIdx.x;
    int rs = id & 63;
    int bh = id >> 6;
    int h = bh % H8;
    int b = bh / H8;
    int w = threadIdx.x;
    int r = rs >> 3, s = rs & 7;

    float f0[9], f1v[9];
#pragma unroll
    for (int k = 0; k < 9; k++) {
        int i = k / 3 - 1, j = k % 3 - 1;
        int hh = h + i, ww = w + j;
        bool ok = (hh >= 0 && hh < H8 && ww >= 0 && ww < W8);
        f0[k]  = ok ? flow[((size_t)(b * 2 + 0) * H8 + hh) * W8 + ww] : 0.f;
        f1v[k] = ok ? flow[((size_t)(b * 2 + 1) * H8 + hh) * W8 + ww] : 0.f;
    }
    float e[9], sum = 0.f;
#pragma unroll
    for (int k = 0; k < 9; k++) {
        e[k] = __expf(mask[((size_t)(b * 576 + k * 64 + rs) * H8 + h) * W8 + w]);
        sum += e[k];
    }
    float a0 = 0.f, a1 = 0.f;
#pragma unroll
    for (int k = 0; k < 9; k++) { a0 += e[k] * f0[k]; a1 += e[k] * f1v[k]; }
    float inv = 8.0f / sum;
    int y = h * 8 + r, x = w * 8 + s;
    out[((size_t)(b * 2 + 0) * 448 + y) * 768 + x] = a0 * inv;
    out[((size_t)(b * 2 + 1) * 448 + y) * 768 + x] = a1 * inv;
}

// ---------------- launcher ----------------
extern "C" void kernel_launch(void* const* d_in, const int* in_sizes, int n_in,
                              void* d_out, int out_size) {
    const float* fmap1  = (const float*)d_in[0];
    const float* fmap2  = (const float*)d_in[1];
    const float* coords = (const float*)d_in[2];
    const float* flow   = (const float*)d_in[3];
    const float* mask   = (const float*)d_in[4];
    float* out = (float*)d_out;
    float* out_up = out + (size_t)B_ * 324 * HW;

    dim3 cb(32, 32);
    k_convert<<<dim3(HW / 32, C_ / 32, 4), cb>>>(fmap1, fmap2);
    k_gemm<<<dim3(42, 42, 2), 256>>>();
    k_pool_fused<<<NQ, 256>>>();
    k_sample<<<336, dim3(32, 4)>>>(coords, out);
    k_up<<<NQ * 64 / W8, W8>>>(flow, mask, out_up);
}

// round 7
// speedup vs baseline: 1.2569x; 1.0957x over previous
#include <cuda_runtime.h>
#include <cuda_fp16.h>
#include <cstdint>

#define B_  2
#define C_  256
#define H8  56
#define W8  96
#define HW  5376            // H8*W8
#define NQ  (B_*HW)         // 10752 query rows (batch-major)

// ---------------- scratch (static __device__, no allocations) ----------------
__device__ __align__(128) __half g_f1[B_*HW*C_];   // fmap1 [b][n][c] fp16
__device__ __align__(128) __half g_f2[B_*HW*C_];   // fmap2 [b][m][c] fp16
__device__ __align__(128) __half g_c0[57802752];   // 2*5376*5376 level-0 corr
__device__ __align__(128) __half g_c1[NQ*28*48];
__device__ __align__(128) __half g_c2[NQ*14*24];
__device__ __align__(128) __half g_c3[NQ*7*12];

// ---------------- helpers ----------------
__device__ __forceinline__ uint32_t smem_u32(const void* p) {
    return (uint32_t)__cvta_generic_to_shared(p);
}
__device__ __forceinline__ void ldm4(uint32_t& r0, uint32_t& r1, uint32_t& r2, uint32_t& r3,
                                     uint32_t addr) {
    asm volatile("ldmatrix.sync.aligned.m8n8.x4.shared.b16 {%0,%1,%2,%3}, [%4];"
                 : "=r"(r0), "=r"(r1), "=r"(r2), "=r"(r3) : "r"(addr));
}
__device__ __forceinline__ void mma16816(float* c, const uint32_t* a, const uint32_t* b) {
    asm volatile(
        "mma.sync.aligned.m16n8k16.row.col.f32.f16.f16.f32 "
        "{%0,%1,%2,%3},{%4,%5,%6,%7},{%8,%9},{%0,%1,%2,%3};"
        : "+f"(c[0]), "+f"(c[1]), "+f"(c[2]), "+f"(c[3])
        : "r"(a[0]), "r"(a[1]), "r"(a[2]), "r"(a[3]), "r"(b[0]), "r"(b[1]));
}
__device__ __forceinline__ void cpasync16(uint32_t dst, const void* src) {
    asm volatile("cp.async.cg.shared.global [%0], [%1], 16;" :: "r"(dst), "l"(src));
}
__device__ __forceinline__ void cp_commit() {
    asm volatile("cp.async.commit_group;" ::: "memory");
}
template<int N> __device__ __forceinline__ void cp_wait() {
    asm volatile("cp.async.wait_group %0;" :: "n"(N) : "memory");
}

// empty kernel: shifts the profiled launch index onto k_gemm (diagnostics)
__global__ void k_nop() {}

// ---------------- 1) transpose + fp16 convert: [B,C,H,W] -> [B,HW,C] ----------------
__global__ void k_convert(const float* __restrict__ f1, const float* __restrict__ f2) {
    __shared__ float tile[32][33];
    int t = blockIdx.z >> 1;
    int b = blockIdx.z & 1;
    const float* src = t ? f2 : f1;
    __half* dst = t ? g_f2 : g_f1;
    int n0 = blockIdx.x * 32, c0 = blockIdx.y * 32;
    int tx = threadIdx.x, ty = threadIdx.y;
    tile[ty][tx] = src[(size_t)(b * C_ + c0 + ty) * HW + n0 + tx];
    __syncthreads();
    dst[(size_t)(b * HW + n0 + ty) * C_ + c0 + tx] = __float2half_rn(tile[tx][ty]);
}

// ---------------- 2) corr GEMM (HMMA, 4-stage cp.async, smem-staged epilogue) ---------
#define SSTRIDE 40
#define EPSTRIDE 136        // epilogue staging stride (halfs), conflict-free

__global__ __launch_bounds__(256, 2) void k_gemm() {
    __shared__ __align__(16) __half As[4][128 * SSTRIDE];
    __shared__ __align__(16) __half Bs[4][128 * SSTRIDE];
    const int b  = blockIdx.z;
    const int bi = blockIdx.y;
    const int bj = blockIdx.x;
    const int tid  = threadIdx.x;
    const int lane = tid & 31;
    const int wid  = tid >> 5;
    const int wm = (wid & 1) * 64;
    const int wn = (wid >> 1) * 32;

    const __half* Ag = g_f1 + ((size_t)b * HW + (size_t)bi * 128) * C_;
    const __half* Bg = g_f2 + ((size_t)b * HW + (size_t)bj * 128) * C_;

    const int ldrow0 = tid >> 2;
    const int ldrow1 = (tid + 256) >> 2;
    const int ldc16  = (tid & 3) << 3;

    float acc[4][4][4];
#pragma unroll
    for (int i = 0; i < 4; i++)
#pragma unroll
        for (int j = 0; j < 4; j++)
#pragma unroll
            for (int k = 0; k < 4; k++) acc[i][j][k] = 0.f;

#define LOAD_STAGE(kt, s)                                                          \
    {                                                                              \
        const int k0 = (kt) * 32;                                                  \
        cpasync16(smem_u32(&As[s][ldrow0 * SSTRIDE + ldc16]),                      \
                  Ag + ldrow0 * C_ + k0 + ldc16);                                  \
        cpasync16(smem_u32(&As[s][ldrow1 * SSTRIDE + ldc16]),                      \
                  Ag + ldrow1 * C_ + k0 + ldc16);                                  \
        cpasync16(smem_u32(&Bs[s][ldrow0 * SSTRIDE + ldc16]),                      \
                  Bg + ldrow0 * C_ + k0 + ldc16);                                  \
        cpasync16(smem_u32(&Bs[s][ldrow1 * SSTRIDE + ldc16]),                      \
                  Bg + ldrow1 * C_ + k0 + ldc16);                                  \
        cp_commit();                                                               \
    }

    LOAD_STAGE(0, 0);
    LOAD_STAGE(1, 1);
    LOAD_STAGE(2, 2);

#pragma unroll
    for (int kt = 0; kt < 8; kt++) {
        cp_wait<2>();
        __syncthreads();     // all warps done with chunk kt-1 -> buffer (kt+3)&3 reusable
        if (kt + 3 < 8) { LOAD_STAGE(kt + 3, (kt + 3) & 3); }
        else            { cp_commit(); }
        const __half* as = As[kt & 3];
        const __half* bs = Bs[kt & 3];
#pragma unroll
        for (int kk = 0; kk < 32; kk += 16) {
            uint32_t a[4][4], bf[4][2];
#pragma unroll
            for (int mi = 0; mi < 4; mi++) {
                int row = wm + mi * 16 + (lane & 15);
                int col = kk + ((lane >> 4) << 3);
                ldm4(a[mi][0], a[mi][1], a[mi][2], a[mi][3],
                     smem_u32(as + row * SSTRIDE + col));
            }
#pragma unroll
            for (int nb = 0; nb < 2; nb++) {
                int row = wn + nb * 16 + (lane & 7) + ((lane >> 4) << 3);
                int col = kk + (((lane >> 3) & 1) << 3);
                uint32_t r0, r1, r2, r3;
                ldm4(r0, r1, r2, r3, smem_u32(bs + row * SSTRIDE + col));
                bf[nb * 2][0] = r0; bf[nb * 2][1] = r1;
                bf[nb * 2 + 1][0] = r2; bf[nb * 2 + 1][1] = r3;
            }
#pragma unroll
            for (int mi = 0; mi < 4; mi++)
#pragma unroll
                for (int ni = 0; ni < 4; ni++)
                    mma16816(acc[mi][ni], a[mi], bf[ni]);
        }
    }

    // ---- epilogue: acc -> smem stage (conflict-free) -> coalesced st.128 ----
    __syncthreads();                       // all warps done reading As/Bs
    __half* stage = &As[0][0];             // 128 x EPSTRIDE halfs = 34816 B (< 40960)
    const float s = 0.0625f;               // 1/sqrt(256)
#pragma unroll
    for (int mi = 0; mi < 4; mi++) {
#pragma unroll
        for (int ni = 0; ni < 4; ni++) {
            int r0 = wm + mi * 16 + (lane >> 2);
            int c0 = wn + ni * 8 + (lane & 3) * 2;
            *(__half2*)(stage + r0 * EPSTRIDE + c0) =
                __floats2half2_rn(acc[mi][ni][0] * s, acc[mi][ni][1] * s);
            *(__half2*)(stage + (r0 + 8) * EPSTRIDE + c0) =
                __floats2half2_rn(acc[mi][ni][2] * s, acc[mi][ni][3] * s);
        }
    }
    __syncthreads();
    const size_t rowb = (size_t)b * HW + (size_t)bi * 128;
#pragma unroll
    for (int it = 0; it < 8; it++) {
        int r  = wid * 16 + it * 2 + (lane >> 4);   // 0..127
        int ci = lane & 15;                         // int4 index within 256B row
        int4 v = *(const int4*)(stage + r * EPSTRIDE + ci * 8);
        *(int4*)(g_c0 + (rowb + r) * HW + (size_t)bj * 128 + ci * 8) = v;
    }
}

// ---------------- 3) fused pyramid pool: c0 row -> l1,l2,l3 ----------------
__global__ void k_pool_fused() {
    __shared__ __align__(16) __half s0[56 * 96];
    __shared__ __half s1[28 * 48];
    __shared__ __half s2[14 * 24];
    int n = blockIdx.x;
    int tid = threadIdx.x;
    const int4* src = (const int4*)(g_c0 + (size_t)n * 5376);
    int4* s0v = (int4*)s0;
#pragma unroll
    for (int i = tid; i < 672; i += 256) s0v[i] = src[i];
    __syncthreads();
    for (int i = tid; i < 1344; i += 256) {
        int x = i % 48, y = i / 48;
        float v = 0.25f * (__half2float(s0[(2 * y) * 96 + 2 * x]) +
                           __half2float(s0[(2 * y) * 96 + 2 * x + 1]) +
                           __half2float(s0[(2 * y + 1) * 96 + 2 * x]) +
                           __half2float(s0[(2 * y + 1) * 96 + 2 * x + 1]));
        __half h = __float2half_rn(v);
        s1[i] = h;
        g_c1[(size_t)n * 1344 + i] = h;
    }
    __syncthreads();
    for (int i = tid; i < 336; i += 256) {
        int x = i % 24, y = i / 24;
        float v = 0.25f * (__half2float(s1[(2 * y) * 48 + 2 * x]) +
                           __half2float(s1[(2 * y) * 48 + 2 * x + 1]) +
                           __half2float(s1[(2 * y + 1) * 48 + 2 * x]) +
                           __half2float(s1[(2 * y + 1) * 48 + 2 * x + 1]));
        __half h = __float2half_rn(v);
        s2[i] = h;
        g_c2[(size_t)n * 336 + i] = h;
    }
    __syncthreads();
    if (tid < 84) {
        int x = tid % 12, y = tid / 12;
        float v = 0.25f * (__half2float(s2[(2 * y) * 24 + 2 * x]) +
                           __half2float(s2[(2 * y) * 24 + 2 * x + 1]) +
                           __half2float(s2[(2 * y + 1) * 24 + 2 * x]) +
                           __half2float(s2[(2 * y + 1) * 24 + 2 * x + 1]));
        g_c3[(size_t)n * 84 + tid] = __float2half_rn(v);
    }
}

// ---------------- 4) pyramid sampling, coalesced stores -> [B,324,H8,W8] ----------------
__global__ __launch_bounds__(128) void k_sample(const float* __restrict__ coords,
                                                float* __restrict__ out) {
    __shared__ __half swin[4][100][32];
    int blk = blockIdx.x;            // 2*56*3 = 336
    int wseg = blk % 3;
    int h = (blk / 3) % H8;
    int b = blk / (3 * H8);
    int tx = threadIdx.x;            // pixel within 32-segment
    int L  = threadIdx.y;            // level
    int w = wseg * 32 + tx;
    int nq = h * W8 + w;

    float cx = coords[(size_t)(b * 2 + 0) * HW + nq];
    float cy = coords[(size_t)(b * 2 + 1) * HW + nq];

    const __half* cl; int Hl, Wl;
    if (L == 0)      { cl = g_c0; Hl = 56; Wl = 96; }
    else if (L == 1) { cl = g_c1; Hl = 28; Wl = 48; }
    else if (L == 2) { cl = g_c2; Hl = 14; Wl = 24; }
    else             { cl = g_c3; Hl = 7;  Wl = 12; }

    float inv = 1.0f / (float)(1 << L);
    float fx = cx * inv, fy = cy * inv;
    float fxf = floorf(fx), fyf = floorf(fy);
    float wx = fx - fxf, wy = fy - fyf;
    int bx = (int)fxf - 4, by = (int)fyf - 4;

    const __half* base = cl + (size_t)(b * HW + nq) * (Hl * Wl);
#pragma unroll
    for (int ly = 0; ly < 10; ly++) {
        int gy = by + ly;
        bool yok = (gy >= 0) & (gy < Hl);
        const __half* rowp = base + gy * Wl;
#pragma unroll
        for (int lx = 0; lx < 10; lx++) {
            int gx = bx + lx;
            __half v = __float2half_rn(0.f);
            if (yok && gx >= 0 && gx < Wl) v = rowp[gx];
            swin[L][ly * 10 + lx][tx] = v;
        }
    }
    __syncthreads();

    float* outbase = out + ((size_t)(b * 324 + L * 81) * H8 + h) * W8 + w;
#pragma unroll 3
    for (int o = 0; o < 81; o++) {
        int xo = o / 9;              // x varies along axis 0 (torch meshgrid quirk)
        int yo = o % 9;
        float v00 = __half2float(swin[L][yo * 10 + xo][tx]);
        float v10 = __half2float(swin[L][yo * 10 + xo + 1][tx]);
        float v01 = __half2float(swin[L][(yo + 1) * 10 + xo][tx]);
        float v11 = __half2float(swin[L][(yo + 1) * 10 + xo + 1][tx]);
        float v = (1.f - wy) * ((1.f - wx) * v00 + wx * v10)
                +        wy  * ((1.f - wx) * v01 + wx * v11);
        outbase[(size_t)o * HW] = v;
    }
}

// ---------------- 5) convex upsample -> [B,2,448,768] ----------------
__global__ void k_up(const float* __restrict__ flow, const float* __restrict__ mask,
                     float* __restrict__ out) {
    int id = blockIdx.x;
    int rs = id & 63;
    int bh = id >> 6;
    int h = bh % H8;
    int b = bh / H8;
    int w = threadIdx.x;
    int r = rs >> 3, s = rs & 7;

    float f0[9], f1v[9];
#pragma unroll
    for (int k = 0; k < 9; k++) {
        int i = k / 3 - 1, j = k % 3 - 1;
        int hh = h + i, ww = w + j;
        bool ok = (hh >= 0 && hh < H8 && ww >= 0 && ww < W8);
        f0[k]  = ok ? flow[((size_t)(b * 2 + 0) * H8 + hh) * W8 + ww] : 0.f;
        f1v[k] = ok ? flow[((size_t)(b * 2 + 1) * H8 + hh) * W8 + ww] : 0.f;
    }
    float e[9], sum = 0.f;
#pragma unroll
    for (int k = 0; k < 9; k++) {
        e[k] = __expf(mask[((size_t)(b * 576 + k * 64 + rs) * H8 + h) * W8 + w]);
        sum += e[k];
    }
    float a0 = 0.f, a1 = 0.f;
#pragma unroll
    for (int k = 0; k < 9; k++) { a0 += e[k] * f0[k]; a1 += e[k] * f1v[k]; }
    float inv = 8.0f / sum;
    int y = h * 8 + r, x = w * 8 + s;
    out[((size_t)(b * 2 + 0) * 448 + y) * 768 + x] = a0 * inv;
    out[((size_t)(b * 2 + 1) * 448 + y) * 768 + x] = a1 * inv;
}

// ---------------- launcher ----------------
extern "C" void kernel_launch(void* const* d_in, const int* in_sizes, int n_in,
                              void* d_out, int out_size) {
    const float* fmap1  = (const float*)d_in[0];
    const float* fmap2  = (const float*)d_in[1];
    const float* coords = (const float*)d_in[2];
    const float* flow   = (const float*)d_in[3];
    const float* mask   = (const float*)d_in[4];
    float* out = (float*)d_out;
    float* out_up = out + (size_t)B_ * 324 * HW;

    dim3 cb(32, 32);
    k_convert<<<dim3(HW / 32, C_ / 32, 4), cb>>>(fmap1, fmap2);     // idx 0
    k_nop<<<1, 32>>>();                                             // idx 1
    k_nop<<<1, 32>>>();                                             // idx 2
    k_gemm<<<dim3(42, 42, 2), 256>>>();                             // idx 3 (profiled)
    k_pool_fused<<<NQ, 256>>>();                                    // idx 4
    k_sample<<<336, dim3(32, 4)>>>(coords, out);                    // idx 5
    k_up<<<NQ * 64 / W8, W8>>>(flow, mask, out_up);                 // idx 6
}